// round 14
// baseline (speedup 1.0000x reference)
#include <cuda_runtime.h>
#include <cuda_bf16.h>
#include <cstdint>

// ---------------- problem constants ----------------
#define SS    1024
#define INW   32
#define HH    128
#define NTHR  256          // 8 warps; warp w owns gates w*64 .. w*64+63 (4 m-tiles, full K)
#define NBLK  128          // 4 batch rows per CTA
#define KTOT  160          // 128 h + 32 x
#define NKT   10           // k16 tiles (bf16 set)
#define NKQ   5            // k32 tiles (fp8 set)
#define BST   168          // bf16 B staging stride in bf16 elems (conflict-free)
// bf16 staging: 8 rows; rows 0..3 = hi(batch 0..3), rows 4..7 = lo(batch 0..3)
#define BSTAGE_BYTES (8 * BST * 2)
#define B8ST  176          // fp8 B staging stride in bytes (8 rows; rows 4..7 zero)
#define B8_BYTES (8 * B8ST)
#define GSTR  10           // gbuf stride in floats (conflict-free mod 32)

#define OFF_A8     0
#define A8_BYTES   (8 * 4 * NKQ * 32 * 16)     // 81920: W_lo e4m3 fragments (x256)
#define OFF_B      A8_BYTES                     // 81920
#define OFF_B8     (OFF_B + BSTAGE_BYTES)      // 84608
#define OFF_GBUF   (OFF_B8 + B8_BYTES)         // 86016: float[512][GSTR]
#define OFF_LRED   (OFF_GBUF + 512 * GSTR * 4) // 106496
#define SMEM_BYTES (OFF_LRED + 256)            // 106752

// ---------------- helpers ----------------
__device__ __forceinline__ unsigned short bf16_bits(float v) {
    __nv_bfloat16 b = __float2bfloat16(v);
    return *reinterpret_cast<unsigned short*>(&b);
}
__device__ __forceinline__ float bf16_val(unsigned short s) {
    __nv_bfloat16 b = *reinterpret_cast<__nv_bfloat16*>(&s);
    return __bfloat162float(b);
}
__device__ __forceinline__ void split_bf16(float w, unsigned short& hi, unsigned short& lo) {
    hi = bf16_bits(w);
    lo = bf16_bits(w - bf16_val(hi));
}
__device__ __forceinline__ uint32_t pack2(unsigned short a16, unsigned short b16) {
    return (uint32_t)a16 | ((uint32_t)b16 << 16);
}
// pack two floats -> e4m3x2; first operand lands in the UPPER byte
__device__ __forceinline__ unsigned short cvt_e4m3x2(float hi_byte, float lo_byte) {
    unsigned short r;
    asm("cvt.rn.satfinite.e4m3x2.f32 %0, %1, %2;" : "=h"(r) : "f"(hi_byte), "f"(lo_byte));
    return r;
}
__device__ __forceinline__ uint32_t pack4_e4m3(float k0, float k1, float k2, float k3) {
    return (uint32_t)cvt_e4m3x2(k1, k0) | ((uint32_t)cvt_e4m3x2(k3, k2) << 16);
}
__device__ __forceinline__ void mma_bf16(float& d0, float& d1, float& d2, float& d3,
                                         uint32_t a0, uint32_t a1, uint32_t a2, uint32_t a3,
                                         uint32_t b0, uint32_t b1) {
    asm volatile(
        "mma.sync.aligned.m16n8k16.row.col.f32.bf16.bf16.f32 "
        "{%0,%1,%2,%3}, {%4,%5,%6,%7}, {%8,%9}, {%0,%1,%2,%3};"
        : "+f"(d0), "+f"(d1), "+f"(d2), "+f"(d3)
        : "r"(a0), "r"(a1), "r"(a2), "r"(a3), "r"(b0), "r"(b1));
}
__device__ __forceinline__ void mma_fp8(float& d0, float& d1, float& d2, float& d3,
                                        uint32_t a0, uint32_t a1, uint32_t a2, uint32_t a3,
                                        uint32_t b0, uint32_t b1) {
    asm volatile(
        "mma.sync.aligned.m16n8k32.row.col.f32.e4m3.e4m3.f32 "
        "{%0,%1,%2,%3}, {%4,%5,%6,%7}, {%8,%9}, {%0,%1,%2,%3};"
        : "+f"(d0), "+f"(d1), "+f"(d2), "+f"(d3)
        : "r"(a0), "r"(a1), "r"(a2), "r"(a3), "r"(b0), "r"(b1));
}
__device__ __forceinline__ float sigmoid_f(float v) {
    return __fdividef(1.0f, 1.0f + __expf(-v));
}
__device__ __forceinline__ float tanh_f(float v) {
    return 1.0f - __fdividef(2.0f, __expf(2.0f * v) + 1.0f);
}

__global__ void __launch_bounds__(NTHR, 1)
lstm_mma_kernel(const float* __restrict__ x,     // [B,S,IN]
                const float* __restrict__ Wih,   // [4H,IN]
                const float* __restrict__ Whh,   // [4H,H]
                const float* __restrict__ bih,   // [4H]
                const float* __restrict__ bhh,   // [4H]
                const float* __restrict__ Wlin,  // [1, S*H]
                const float* __restrict__ blin,  // [1]
                float* __restrict__ out)         // [B,1]
{
    extern __shared__ char smc[];
    float* smf = reinterpret_cast<float*>(smc);
    const int tid  = threadIdx.x;
    const int wid  = tid >> 5;
    const int lane = tid & 31;
    const int b0   = blockIdx.x * 4;

    // ---------------- prologue ----------------
    for (int i = tid; i < BSTAGE_BYTES / 4; i += NTHR)
        reinterpret_cast<uint32_t*>(smc + OFF_B)[i] = 0;
    for (int i = tid; i < B8_BYTES / 4; i += NTHR)
        reinterpret_cast<uint32_t*>(smc + OFF_B8)[i] = 0;
    if (tid < 64) smf[(OFF_LRED >> 2) + tid] = 0.0f;

    // W_hi bf16 fragments -> registers (4 mt x 10 kt x 4 = 160 regs)
    uint32_t wa[4][NKT][4];
    {
        const int r  = lane >> 2;
        const int kc = (lane & 3) * 2;
        #pragma unroll
        for (int mt = 0; mt < 4; mt++) {
            #pragma unroll
            for (int kt = 0; kt < NKT; kt++) {
                #pragma unroll
                for (int rg = 0; rg < 4; rg++) {
                    int g = wid * 64 + mt * 16 + r + ((rg & 1) ? 8 : 0);
                    int k = kt * 16 + kc + ((rg & 2) ? 8 : 0);
                    float2 w2;
                    if (k < HH) w2 = *reinterpret_cast<const float2*>(Whh + (size_t)g * HH + k);
                    else        w2 = *reinterpret_cast<const float2*>(Wih + (size_t)g * INW + (k - HH));
                    wa[mt][kt][rg] = pack2(bf16_bits(w2.x), bf16_bits(w2.y));
                }
            }
        }
    }
    // W_lo e4m3 fragments (scaled x256) -> smem A8, m16n8k32 A layout
    {
        const int r   = lane >> 2;
        const int kc4 = (lane & 3) * 4;
        #pragma unroll
        for (int mt = 0; mt < 4; mt++) {
            #pragma unroll
            for (int kq = 0; kq < NKQ; kq++) {
                uint32_t frag[4];
                #pragma unroll
                for (int rg = 0; rg < 4; rg++) {
                    int g = wid * 64 + mt * 16 + r + ((rg & 1) ? 8 : 0);
                    int k = kq * 32 + kc4 + ((rg & 2) ? 16 : 0);
                    float4 w4;
                    if (k < HH) w4 = *reinterpret_cast<const float4*>(Whh + (size_t)g * HH + k);
                    else        w4 = *reinterpret_cast<const float4*>(Wih + (size_t)g * INW + (k - HH));
                    float l0 = (w4.x - bf16_val(bf16_bits(w4.x))) * 256.0f;
                    float l1 = (w4.y - bf16_val(bf16_bits(w4.y))) * 256.0f;
                    float l2 = (w4.z - bf16_val(bf16_bits(w4.z))) * 256.0f;
                    float l3 = (w4.w - bf16_val(bf16_bits(w4.w))) * 256.0f;
                    frag[rg] = pack4_e4m3(l0, l1, l2, l3);
                }
                *reinterpret_cast<uint4*>(smc + OFF_A8 +
                    (size_t)((((wid * 4 + mt) * NKQ + kq) * 32 + lane) * 16))
                    = make_uint4(frag[0], frag[1], frag[2], frag[3]);
            }
        }
    }

    // ew role: thread owns units (j0, j0+1) of batch row n
    const int j0 = (tid >> 2) * 2;
    const int n  = tid & 3;
    const float bi0 = bih[j0]           + bhh[j0];
    const float bi1 = bih[j0 + 1]       + bhh[j0 + 1];
    const float bf0 = bih[j0 + 128]     + bhh[j0 + 128];
    const float bf1 = bih[j0 + 129]     + bhh[j0 + 129];
    const float bg0 = bih[j0 + 256]     + bhh[j0 + 256];
    const float bg1 = bih[j0 + 257]     + bhh[j0 + 257];
    const float bo0 = bih[j0 + 384]     + bhh[j0 + 384];
    const float bo1 = bih[j0 + 385]     + bhh[j0 + 385];
    float c0 = 0.0f, c1 = 0.0f;
    float lin = 0.0f;

    __syncthreads();                       // staging zero complete
    if (tid < 64) {                        // x(t=0)
        int row = tid >> 4, i0 = (tid & 15) * 2;
        float2 xv = *reinterpret_cast<const float2*>(
            x + ((size_t)(b0 + row) * SS + 0) * INW + i0);
        unsigned short h0, l0, h1, l1;
        split_bf16(xv.x, h0, l0);
        split_bf16(xv.y, h1, l1);
        *reinterpret_cast<uint32_t*>(smc + OFF_B + (size_t)(row * BST + HH + i0) * 2)
            = pack2(h0, h1);
        *reinterpret_cast<uint32_t*>(smc + OFF_B + (size_t)((row + 4) * BST + HH + i0) * 2)
            = pack2(l0, l1);
        *reinterpret_cast<unsigned short*>(smc + OFF_B8 + row * B8ST + HH + i0)
            = cvt_e4m3x2(xv.y, xv.x);
    }
    __syncthreads();

    const int bn  = lane >> 2;             // B fragment column 0..7
    const int bk  = (lane & 3) * 2;
    const int bk4 = (lane & 3) * 4;

    // ---------------- main recurrence ----------------
    #pragma unroll 1
    for (int t = 0; t < SS; t++) {
        const float2 wl2 = __ldg(reinterpret_cast<const float2*>(
            Wlin + (size_t)t * HH + j0));
        float2 xv = make_float2(0.0f, 0.0f);
        if (tid < 64) {
            int row = tid >> 4, i0 = (tid & 15) * 2;
            int tn = (t + 1 < SS) ? (t + 1) : (SS - 1);
            xv = *reinterpret_cast<const float2*>(
                x + ((size_t)(b0 + row) * SS + tn) * INW + i0);
        }

        // === MMA set 1: bf16 W_hi x B[hi|lo] ===
        float d0[4], d1[4], d2[4], d3[4];
        #pragma unroll
        for (int mt = 0; mt < 4; mt++) { d0[mt] = 0.f; d1[mt] = 0.f; d2[mt] = 0.f; d3[mt] = 0.f; }

        #pragma unroll
        for (int kt = 0; kt < NKT; kt++) {
            const char* bb = smc + OFF_B + (size_t)((bn * BST + kt * 16 + bk) * 2);
            uint32_t bb0 = *reinterpret_cast<const uint32_t*>(bb);
            uint32_t bb1 = *reinterpret_cast<const uint32_t*>(bb + 16);
            #pragma unroll
            for (int mt = 0; mt < 4; mt++)
                mma_bf16(d0[mt], d1[mt], d2[mt], d3[mt],
                         wa[mt][kt][0], wa[mt][kt][1], wa[mt][kt][2], wa[mt][kt][3],
                         bb0, bb1);
        }
        // === MMA set 2: fp8 W_lo(x256) x B8_hi ===
        float e0[4], e1[4], e2[4], e3[4];
        #pragma unroll
        for (int mt = 0; mt < 4; mt++) { e0[mt] = 0.f; e1[mt] = 0.f; e2[mt] = 0.f; e3[mt] = 0.f; }
        #pragma unroll
        for (int kq = 0; kq < NKQ; kq++) {
            const char* bb = smc + OFF_B8 + (size_t)(bn * B8ST + kq * 32 + bk4);
            uint32_t b80 = *reinterpret_cast<const uint32_t*>(bb);
            uint32_t b81 = *reinterpret_cast<const uint32_t*>(bb + 16);
            #pragma unroll
            for (int mt = 0; mt < 4; mt++) {
                const uint4 a8 = *reinterpret_cast<const uint4*>(smc + OFF_A8 +
                    (size_t)((((wid * 4 + mt) * NKQ + kq) * 32 + lane) * 16));
                mma_fp8(e0[mt], e1[mt], e2[mt], e3[mt],
                        a8.x, a8.y, a8.z, a8.w, b80, b81);
            }
        }

        // cross-column reduce for set 1: preact(n) = D[col n] + D[col n+4]
        #pragma unroll
        for (int mt = 0; mt < 4; mt++) {
            d0[mt] += __shfl_xor_sync(0xffffffffu, d0[mt], 2);
            d1[mt] += __shfl_xor_sync(0xffffffffu, d1[mt], 2);
            d2[mt] += __shfl_xor_sync(0xffffffffu, d2[mt], 2);
            d3[mt] += __shfl_xor_sync(0xffffffffu, d3[mt], 2);
        }
        // store D + 2^-8 * E (cols 0..3 in lanes lane%4 < 2; E cols 4..7 are zero)
        if ((lane & 2) == 0) {
            const float s = 0.00390625f;   // 2^-8
            const int c = (lane & 3) * 2;
            const int r = lane >> 2;
            #pragma unroll
            for (int mt = 0; mt < 4; mt++) {
                int gm = wid * 64 + mt * 16 + r;
                *reinterpret_cast<float2*>(smf + (OFF_GBUF >> 2) + gm * GSTR + c)
                    = make_float2(fmaf(e0[mt], s, d0[mt]), fmaf(e1[mt], s, d1[mt]));
                *reinterpret_cast<float2*>(smf + (OFF_GBUF >> 2) + (gm + 8) * GSTR + c)
                    = make_float2(fmaf(e2[mt], s, d2[mt]), fmaf(e3[mt], s, d3[mt]));
            }
        }
        __syncthreads();

        // === elementwise: units j0, j0+1 of row n ===
        {
            const float* gb = smf + (OFF_GBUF >> 2) + n;
            float pi0 = gb[(j0)       * GSTR] + bi0;
            float pi1 = gb[(j0 + 1)   * GSTR] + bi1;
            float pf0 = gb[(j0 + 128) * GSTR] + bf0;
            float pf1 = gb[(j0 + 129) * GSTR] + bf1;
            float pg0 = gb[(j0 + 256) * GSTR] + bg0;
            float pg1 = gb[(j0 + 257) * GSTR] + bg1;
            float po0 = gb[(j0 + 384) * GSTR] + bo0;
            float po1 = gb[(j0 + 385) * GSTR] + bo1;

            float iv0 = sigmoid_f(pi0), iv1 = sigmoid_f(pi1);
            float fv0 = sigmoid_f(pf0), fv1 = sigmoid_f(pf1);
            float gv0 = tanh_f(pg0),    gv1 = tanh_f(pg1);
            float ov0 = sigmoid_f(po0), ov1 = sigmoid_f(po1);
            c0 = fmaf(fv0, c0, iv0 * gv0);
            c1 = fmaf(fv1, c1, iv1 * gv1);
            float hv0 = ov0 * tanh_f(c0);
            float hv1 = ov1 * tanh_f(c1);
            lin = fmaf(hv0, wl2.x, fmaf(hv1, wl2.y, lin));

            unsigned short h0, l0, h1, l1;
            split_bf16(hv0, h0, l0);
            split_bf16(hv1, h1, l1);
            *reinterpret_cast<uint32_t*>(smc + OFF_B + (size_t)(n * BST + j0) * 2)
                = pack2(h0, h1);
            *reinterpret_cast<uint32_t*>(smc + OFF_B + (size_t)((n + 4) * BST + j0) * 2)
                = pack2(l0, l1);
            *reinterpret_cast<unsigned short*>(smc + OFF_B8 + n * B8ST + j0)
                = cvt_e4m3x2(hv1, hv0);
        }
        if (tid < 64) {
            int row = tid >> 4, i0 = (tid & 15) * 2;
            unsigned short h0, l0, h1, l1;
            split_bf16(xv.x, h0, l0);
            split_bf16(xv.y, h1, l1);
            *reinterpret_cast<uint32_t*>(smc + OFF_B + (size_t)(row * BST + HH + i0) * 2)
                = pack2(h0, h1);
            *reinterpret_cast<uint32_t*>(smc + OFF_B + (size_t)((row + 4) * BST + HH + i0) * 2)
                = pack2(l0, l1);
            *reinterpret_cast<unsigned short*>(smc + OFF_B8 + row * B8ST + HH + i0)
                = cvt_e4m3x2(xv.y, xv.x);
        }
        __syncthreads();
    }

    // ---------------- epilogue ----------------
    float v = lin;
    #pragma unroll
    for (int off = 4; off <= 16; off <<= 1) v += __shfl_xor_sync(0xffffffffu, v, off);
    if (lane < 4) smf[(OFF_LRED >> 2) + wid * 4 + lane] = v;   // lane == n
    __syncthreads();
    if (tid < 4) {
        float s = blin[0];
        #pragma unroll
        for (int w = 0; w < 8; w++) s += smf[(OFF_LRED >> 2) + w * 4 + tid];
        out[b0 + tid] = s;
    }
}

extern "C" void kernel_launch(void* const* d_in, const int* in_sizes, int n_in,
                              void* d_out, int out_size)
{
    const float* x    = (const float*)d_in[0];
    const float* Wih  = (const float*)d_in[1];
    const float* Whh  = (const float*)d_in[2];
    const float* bih  = (const float*)d_in[3];
    const float* bhh  = (const float*)d_in[4];
    const float* Wlin = (const float*)d_in[5];
    const float* blin = (const float*)d_in[6];
    float* out = (float*)d_out;

    cudaFuncSetAttribute(lstm_mma_kernel,
                         cudaFuncAttributeMaxDynamicSharedMemorySize, SMEM_BYTES);
    lstm_mma_kernel<<<NBLK, NTHR, SMEM_BYTES>>>(x, Wih, Whh, bih, bhh, Wlin, blin, out);
}

// round 15
// speedup vs baseline: 1.5437x; 1.5437x over previous
#include <cuda_runtime.h>
#include <cuda_bf16.h>
#include <cstdint>

// ---------------- problem constants ----------------
#define SS    1024
#define INW   32
#define HH    128
#define NTHR  256          // 8 warps; warp w owns all 4 gate types of units w*16..w*16+15
#define NBLK  128          // 4 batch rows per CTA
#define KTOT  160          // 128 h + 32 x
#define NKT   10           // k16 tiles
#define BST   168          // B staging stride in bf16 (conflict-free)
// staging: 8 rows; rows 0..3 = hi(batch 0..3), rows 4..7 = lo(batch 0..3)
#define BSTAGE_BYTES (8 * BST * 2)      // 2688, x2 ping-pong

#define OFF_ALO    0
#define ALO_BYTES  (512 * KTOT * 2)            // 163840: W_lo bf16 fragments
#define OFF_B      ALO_BYTES                    // 163840: 2 ping-pong staging buffers
#define OFF_LRED   (OFF_B + 2 * BSTAGE_BYTES)  // 169216
#define SMEM_BYTES (OFF_LRED + 256)            // 169472

// ---------------- helpers ----------------
__device__ __forceinline__ unsigned short bf16_bits(float v) {
    __nv_bfloat16 b = __float2bfloat16(v);
    return *reinterpret_cast<unsigned short*>(&b);
}
__device__ __forceinline__ float bf16_val(unsigned short s) {
    __nv_bfloat16 b = *reinterpret_cast<__nv_bfloat16*>(&s);
    return __bfloat162float(b);
}
__device__ __forceinline__ void split_bf16(float w, unsigned short& hi, unsigned short& lo) {
    hi = bf16_bits(w);
    lo = bf16_bits(w - bf16_val(hi));
}
__device__ __forceinline__ uint32_t pack2(unsigned short a16, unsigned short b16) {
    return (uint32_t)a16 | ((uint32_t)b16 << 16);
}
__device__ __forceinline__ void mma_bf16(float& d0, float& d1, float& d2, float& d3,
                                         uint32_t a0, uint32_t a1, uint32_t a2, uint32_t a3,
                                         uint32_t b0, uint32_t b1) {
    asm volatile(
        "mma.sync.aligned.m16n8k16.row.col.f32.bf16.bf16.f32 "
        "{%0,%1,%2,%3}, {%4,%5,%6,%7}, {%8,%9}, {%0,%1,%2,%3};"
        : "+f"(d0), "+f"(d1), "+f"(d2), "+f"(d3)
        : "r"(a0), "r"(a1), "r"(a2), "r"(a3), "r"(b0), "r"(b1));
}
__device__ __forceinline__ float sigmoid_f(float v) {
    return __fdividef(1.0f, 1.0f + __expf(-v));
}
__device__ __forceinline__ float tanh_f(float v) {
    return 1.0f - __fdividef(2.0f, __expf(2.0f * v) + 1.0f);
}

__global__ void __launch_bounds__(NTHR, 1)
lstm_mma_kernel(const float* __restrict__ x,     // [B,S,IN]
                const float* __restrict__ Wih,   // [4H,IN]
                const float* __restrict__ Whh,   // [4H,H]
                const float* __restrict__ bih,   // [4H]
                const float* __restrict__ bhh,   // [4H]
                const float* __restrict__ Wlin,  // [1, S*H]
                const float* __restrict__ blin,  // [1]
                float* __restrict__ out)         // [B,1]
{
    extern __shared__ char smc[];
    float* smf = reinterpret_cast<float*>(smc);
    const int tid  = threadIdx.x;
    const int wid  = tid >> 5;
    const int lane = tid & 31;
    const int b0   = blockIdx.x * 4;

    // ---------------- prologue ----------------
    for (int i = tid; i < (2 * BSTAGE_BYTES) / 4; i += NTHR)
        reinterpret_cast<uint32_t*>(smc + OFF_B)[i] = 0;
    if (tid < 64) smf[(OFF_LRED >> 2) + tid] = 0.0f;

    // W fragments. Warp w, m-tile mt = gate TYPE mt of units w*16..w*16+15:
    //   g = mt*128 + wid*16 + r (+8 for rg&1), k per rg&2.
    // hi -> registers (4 mt x 10 kt x 4 = 160 regs); lo -> smem ALO.
    uint32_t wa[4][NKT][4];
    {
        const int r  = lane >> 2;
        const int kc = (lane & 3) * 2;
        #pragma unroll
        for (int mt = 0; mt < 4; mt++) {
            #pragma unroll
            for (int kt = 0; kt < NKT; kt++) {
                uint32_t lo4[4];
                #pragma unroll
                for (int rg = 0; rg < 4; rg++) {
                    int g = mt * 128 + wid * 16 + r + ((rg & 1) ? 8 : 0);
                    int k = kt * 16 + kc + ((rg & 2) ? 8 : 0);
                    float2 w2;
                    if (k < HH) w2 = *reinterpret_cast<const float2*>(Whh + (size_t)g * HH + k);
                    else        w2 = *reinterpret_cast<const float2*>(Wih + (size_t)g * INW + (k - HH));
                    unsigned short h0, l0, h1, l1;
                    split_bf16(w2.x, h0, l0);
                    split_bf16(w2.y, h1, l1);
                    wa[mt][kt][rg] = pack2(h0, h1);
                    lo4[rg]        = pack2(l0, l1);
                }
                *reinterpret_cast<uint4*>(smc + OFF_ALO +
                    (size_t)((((wid * 4 + mt) * NKT + kt) * 32 + lane) * 16))
                    = make_uint4(lo4[0], lo4[1], lo4[2], lo4[3]);
            }
        }
    }

    // ew role (all 32 lanes): unit u_sel, batch rows n, n+1
    const int u_sel = wid * 16 + (lane >> 2) + ((lane & 2) ? 8 : 0);
    const int n     = 2 * (lane & 1);
    const bool hiD  = (lane & 2) == 0;     // use d0/d1 if true else d2/d3
    float bgt[4];
    #pragma unroll
    for (int mt = 0; mt < 4; mt++)
        bgt[mt] = bih[mt * 128 + u_sel] + bhh[mt * 128 + u_sel];
    float cA = 0.0f, cB = 0.0f;            // c-states for rows n, n+1
    float linA = 0.0f, linB = 0.0f;

    __syncthreads();                       // staging zero complete
    if (tid < 64) {                        // x(t=0) into buf 0
        int row = tid >> 4, i0 = (tid & 15) * 2;
        float2 xv = *reinterpret_cast<const float2*>(
            x + ((size_t)(b0 + row) * SS + 0) * INW + i0);
        unsigned short h0, l0, h1, l1;
        split_bf16(xv.x, h0, l0);
        split_bf16(xv.y, h1, l1);
        *reinterpret_cast<uint32_t*>(smc + OFF_B + (size_t)(row * BST + HH + i0) * 2)
            = pack2(h0, h1);
        *reinterpret_cast<uint32_t*>(smc + OFF_B + (size_t)((row + 4) * BST + HH + i0) * 2)
            = pack2(l0, l1);
    }
    __syncthreads();

    const int bn = lane >> 2;              // B fragment column 0..7
    const int bk = (lane & 3) * 2;

    // ---------------- main recurrence ----------------
    #pragma unroll 1
    for (int t = 0; t < SS; t++) {
        const float wl = __ldg(Wlin + (size_t)t * HH + u_sel);
        float2 xv = make_float2(0.0f, 0.0f);
        if (tid < 64) {
            int row = tid >> 4, i0 = (tid & 15) * 2;
            int tn = (t + 1 < SS) ? (t + 1) : (SS - 1);
            xv = *reinterpret_cast<const float2*>(
                x + ((size_t)(b0 + row) * SS + tn) * INW + i0);
        }

        const char* bbase = smc + OFF_B + (size_t)(t & 1) * BSTAGE_BYTES;

        // === MMA phase: B = [B_hi | B_lo] in the 8 N-columns; 2 A-terms ===
        float d0[4], d1[4], d2[4], d3[4];
        #pragma unroll
        for (int mt = 0; mt < 4; mt++) { d0[mt] = 0.f; d1[mt] = 0.f; d2[mt] = 0.f; d3[mt] = 0.f; }

        #pragma unroll
        for (int kt = 0; kt < NKT; kt++) {
            const char* bb = bbase + (size_t)((bn * BST + kt * 16 + bk) * 2);
            uint32_t bb0 = *reinterpret_cast<const uint32_t*>(bb);
            uint32_t bb1 = *reinterpret_cast<const uint32_t*>(bb + 16);
            #pragma unroll
            for (int mt = 0; mt < 4; mt++)
                mma_bf16(d0[mt], d1[mt], d2[mt], d3[mt],
                         wa[mt][kt][0], wa[mt][kt][1], wa[mt][kt][2], wa[mt][kt][3],
                         bb0, bb1);
            #pragma unroll
            for (int mt = 0; mt < 4; mt++) {
                const uint4 alo = *reinterpret_cast<const uint4*>(smc + OFF_ALO +
                    (size_t)((((wid * 4 + mt) * NKT + kt) * 32 + lane) * 16));
                mma_bf16(d0[mt], d1[mt], d2[mt], d3[mt],
                         alo.x, alo.y, alo.z, alo.w, bb0, bb1);
            }
        }

        // cross-column reduce: xor 2 pairs cols {2q,2q+1}<->{2q+4,2q+5} (hi+lo).
        // After this, EVERY lane holds valid preacts (sum symmetric).
        #pragma unroll
        for (int mt = 0; mt < 4; mt++) {
            d0[mt] += __shfl_xor_sync(0xffffffffu, d0[mt], 2);
            d1[mt] += __shfl_xor_sync(0xffffffffu, d1[mt], 2);
            d2[mt] += __shfl_xor_sync(0xffffffffu, d2[mt], 2);
            d3[mt] += __shfl_xor_sync(0xffffffffu, d3[mt], 2);
        }

        // === in-register elementwise: 2 cells per lane ===
        // lanes q in {0,1}: unit r       -> preacts in d0 (row n), d1 (row n+1)
        // lanes q in {2,3}: unit r+8     -> preacts in d2 (row n), d3 (row n+1)
        char* nbase = smc + OFF_B + (size_t)((t + 1) & 1) * BSTAGE_BYTES;
        {
            float pA[4], pB[4];
            #pragma unroll
            for (int mt = 0; mt < 4; mt++) {
                pA[mt] = (hiD ? d0[mt] : d2[mt]) + bgt[mt];
                pB[mt] = (hiD ? d1[mt] : d3[mt]) + bgt[mt];
            }
            // cell A: (u_sel, row n)
            float ivA = sigmoid_f(pA[0]);
            float fvA = sigmoid_f(pA[1]);
            float gvA = tanh_f(pA[2]);
            float ovA = sigmoid_f(pA[3]);
            cA = fmaf(fvA, cA, ivA * gvA);
            float hvA = ovA * tanh_f(cA);
            linA = fmaf(hvA, wl, linA);
            // cell B: (u_sel, row n+1)
            float ivB = sigmoid_f(pB[0]);
            float fvB = sigmoid_f(pB[1]);
            float gvB = tanh_f(pB[2]);
            float ovB = sigmoid_f(pB[3]);
            cB = fmaf(fvB, cB, ivB * gvB);
            float hvB = ovB * tanh_f(cB);
            linB = fmaf(hvB, wl, linB);

            unsigned short hA, lA, hB, lB;
            split_bf16(hvA, hA, lA);
            split_bf16(hvB, hB, lB);
            *reinterpret_cast<unsigned short*>(nbase + (size_t)(n * BST + u_sel) * 2)       = hA;
            *reinterpret_cast<unsigned short*>(nbase + (size_t)((n + 4) * BST + u_sel) * 2) = lA;
            *reinterpret_cast<unsigned short*>(nbase + (size_t)((n + 1) * BST + u_sel) * 2) = hB;
            *reinterpret_cast<unsigned short*>(nbase + (size_t)((n + 5) * BST + u_sel) * 2) = lB;
        }
        // x(t+1) into next buffer
        if (tid < 64) {
            int row = tid >> 4, i0 = (tid & 15) * 2;
            unsigned short h0, l0, h1, l1;
            split_bf16(xv.x, h0, l0);
            split_bf16(xv.y, h1, l1);
            *reinterpret_cast<uint32_t*>(nbase + (size_t)(row * BST + HH + i0) * 2)
                = pack2(h0, h1);
            *reinterpret_cast<uint32_t*>(nbase + (size_t)((row + 4) * BST + HH + i0) * 2)
                = pack2(l0, l1);
        }
        __syncthreads();                  // single barrier per step
    }

    // ---------------- epilogue ----------------
    // linA = partial for batch row n, linB for row n+1; n = 2*(lane&1).
    // Sum over the 16 lanes sharing lane&1: xor masks {2,4,8,16}.
    #pragma unroll
    for (int off = 2; off <= 16; off <<= 1) {
        linA += __shfl_xor_sync(0xffffffffu, linA, off);
        linB += __shfl_xor_sync(0xffffffffu, linB, off);
    }
    if (lane < 2) {
        smf[(OFF_LRED >> 2) + wid * 4 + 2 * lane]     = linA;   // row 2*lane
        smf[(OFF_LRED >> 2) + wid * 4 + 2 * lane + 1] = linB;   // row 2*lane+1
    }
    __syncthreads();
    if (tid < 4) {
        float s = blin[0];
        #pragma unroll
        for (int w = 0; w < 8; w++) s += smf[(OFF_LRED >> 2) + w * 4 + tid];
        out[b0 + tid] = s;
    }
}

extern "C" void kernel_launch(void* const* d_in, const int* in_sizes, int n_in,
                              void* d_out, int out_size)
{
    const float* x    = (const float*)d_in[0];
    const float* Wih  = (const float*)d_in[1];
    const float* Whh  = (const float*)d_in[2];
    const float* bih  = (const float*)d_in[3];
    const float* bhh  = (const float*)d_in[4];
    const float* Wlin = (const float*)d_in[5];
    const float* blin = (const float*)d_in[6];
    float* out = (float*)d_out;

    cudaFuncSetAttribute(lstm_mma_kernel,
                         cudaFuncAttributeMaxDynamicSharedMemorySize, SMEM_BYTES);
    lstm_mma_kernel<<<NBLK, NTHR, SMEM_BYTES>>>(x, Wih, Whh, bih, bhh, Wlin, blin, out);
}